// round 11
// baseline (speedup 1.0000x reference)
#include <cuda_runtime.h>
#include <cuda_bf16.h>
#include <cstdint>

#define NROWS 65536
#define DDIM  512
#define EDIM  256
#define TDIM  128
#define KDIM  896   // D + E + T
#define NPROTO 5

// Scratch for GEMM output (128 MB). __device__ global per harness rules.
__device__ float g_y[(size_t)NROWS * DDIM];

// ---------------------------------------------------------------------------
// GEMM: g_y[N, 512] = concat(raw, edge, time)[N, 896] @ Wq^T
//   BF16 mma.sync m16n8k16, fp32 smem (cp.async), convert at fragment load.
// ---------------------------------------------------------------------------
constexpr int BM = 128, BN = 128, BK = 32;
constexpr int LDSW  = BK + 4;             // 36-float row stride
constexpr int STAGE = (BM + BN) * LDSW;   // floats per pipeline stage
constexpr int SMEM_BYTES = 2 * STAGE * 4; // 73728 B (double buffered)

__device__ __forceinline__ void cp16(uint32_t saddr, const void* gaddr) {
    asm volatile("cp.async.cg.shared.global [%0], [%1], 16;\n" :: "r"(saddr), "l"(gaddr));
}
__device__ __forceinline__ uint32_t pack2(float2 v) {
    __nv_bfloat162 h = __floats2bfloat162_rn(v.x, v.y);   // v.x -> low half
    return *reinterpret_cast<uint32_t*>(&h);
}

__global__ void __launch_bounds__(256, 2)
gemm_kernel(const float* __restrict__ raw, const float* __restrict__ edge,
            const float* __restrict__ te,  const float* __restrict__ Wq) {
    extern __shared__ float sm[];
    const int tid  = threadIdx.x;
    const int m0   = blockIdx.y * BM;
    const int n0   = blockIdx.x * BN;
    const int warp = tid >> 5, lane = tid & 31;
    const int wm   = warp & 3, wn = warp >> 2;   // 4 warps along M, 2 along N
    const int g    = lane >> 2, t = lane & 3;

    float acc[2][8][4];
    #pragma unroll
    for (int mi = 0; mi < 2; mi++)
        #pragma unroll
        for (int ni = 0; ni < 8; ni++)
            #pragma unroll
            for (int j = 0; j < 4; j++) acc[mi][ni][j] = 0.f;

    auto issue = [&](int kt) {
        float* As = sm + (kt & 1) * STAGE;
        float* Bs = As + BM * LDSW;
        const float* aBase; int stride, col0;
        if (kt < 16)      { aBase = raw;  stride = DDIM; col0 = kt * 32; }
        else if (kt < 24) { aBase = edge; stride = EDIM; col0 = (kt - 16) * 32; }
        else              { aBase = te;   stride = TDIM; col0 = (kt - 24) * 32; }
        #pragma unroll
        for (int i = 0; i < 4; i++) {
            int idx = tid + i * 256;
            int r = idx >> 3, c = (idx & 7) * 4;
            cp16((uint32_t)__cvta_generic_to_shared(As + r * LDSW + c),
                 aBase + (size_t)(m0 + r) * stride + col0 + c);
            cp16((uint32_t)__cvta_generic_to_shared(Bs + r * LDSW + c),
                 Wq + (size_t)(n0 + r) * KDIM + kt * 32 + c);
        }
        asm volatile("cp.async.commit_group;\n");
    };

    issue(0);
    for (int kt = 0; kt < 28; kt++) {
        if (kt < 27) {
            issue(kt + 1);
            asm volatile("cp.async.wait_group 1;\n");
        } else {
            asm volatile("cp.async.wait_group 0;\n");
        }
        __syncthreads();

        const float* As = sm + (kt & 1) * STAGE;
        const float* Bs = As + BM * LDSW;
        #pragma unroll
        for (int ks = 0; ks < 2; ks++) {          // two k16 steps per 32-chunk
            const int kk = ks * 16;
            uint32_t a[2][4], b[8][2];
            #pragma unroll
            for (int mi = 0; mi < 2; mi++) {
                const float* ap = As + (wm * 32 + mi * 16 + g) * LDSW + kk + 2 * t;
                // a0:(g,2t..), a1:(g+8,2t..), a2:(g,2t+8..), a3:(g+8,2t+8..)
                a[mi][0] = pack2(*reinterpret_cast<const float2*>(ap));
                a[mi][1] = pack2(*reinterpret_cast<const float2*>(ap + 8 * LDSW));
                a[mi][2] = pack2(*reinterpret_cast<const float2*>(ap + 8));
                a[mi][3] = pack2(*reinterpret_cast<const float2*>(ap + 8 * LDSW + 8));
            }
            #pragma unroll
            for (int ni = 0; ni < 8; ni++) {
                const float* bp = Bs + (wn * 64 + ni * 8 + g) * LDSW + kk + 2 * t;
                // b0:(k=2t..,n=g), b1:(k=2t+8..,n=g); Bs rows are n, cols are k
                b[ni][0] = pack2(*reinterpret_cast<const float2*>(bp));
                b[ni][1] = pack2(*reinterpret_cast<const float2*>(bp + 8));
            }
            #pragma unroll
            for (int mi = 0; mi < 2; mi++)
                #pragma unroll
                for (int ni = 0; ni < 8; ni++) {
                    float* c = acc[mi][ni];
                    asm volatile(
                        "mma.sync.aligned.m16n8k16.row.col.f32.bf16.bf16.f32 "
                        "{%0,%1,%2,%3}, {%4,%5,%6,%7}, {%8,%9}, {%0,%1,%2,%3};\n"
                        : "+f"(c[0]), "+f"(c[1]), "+f"(c[2]), "+f"(c[3])
                        : "r"(a[mi][0]), "r"(a[mi][1]), "r"(a[mi][2]), "r"(a[mi][3]),
                          "r"(b[ni][0]), "r"(b[ni][1]));
                }
        }
        __syncthreads();
    }

    // Writeback (c0,c1 adjacent columns -> float2)
    #pragma unroll
    for (int mi = 0; mi < 2; mi++) {
        int r0 = m0 + wm * 32 + mi * 16 + g;
        #pragma unroll
        for (int ni = 0; ni < 8; ni++) {
            int c = n0 + wn * 64 + ni * 8 + t * 2;
            *reinterpret_cast<float2*>(g_y + (size_t)r0 * DDIM + c) =
                make_float2(acc[mi][ni][0], acc[mi][ni][1]);
            *reinterpret_cast<float2*>(g_y + (size_t)(r0 + 8) * DDIM + c) =
                make_float2(acc[mi][ni][2], acc[mi][ni][3]);
        }
    }
}

// ---------------------------------------------------------------------------
// Fused epilogue: ONE WARP per row, zero __syncthreads (validated in R6).
// ---------------------------------------------------------------------------
__device__ __forceinline__ float wredsum(float x) {
    #pragma unroll
    for (int o = 16; o > 0; o >>= 1) x += __shfl_xor_sync(0xffffffffu, x, o);
    return x;
}
__device__ __forceinline__ float clampf(float x, float a) { return fminf(fmaxf(x, -a), a); }
__device__ __forceinline__ float4 c4(float4 v, float a) {
    return make_float4(clampf(v.x,a), clampf(v.y,a), clampf(v.z,a), clampf(v.w,a));
}

constexpr int EPI_WARPS = 4;   // rows per block

__global__ void __launch_bounds__(EPI_WARPS * 32)
epilogue_kernel(const float* __restrict__ raw, const float* __restrict__ te,
                const float* __restrict__ protos, const float* __restrict__ bq,
                const float* __restrict__ Wg, const float* __restrict__ bg,
                const float* __restrict__ gam, const float* __restrict__ bet,
                const float* __restrict__ temperature, float* __restrict__ out) {
    const int lane = threadIdx.x & 31;
    const int row  = blockIdx.x * EPI_WARPS + (threadIdx.x >> 5);
    const size_t base4 = (size_t)row * (DDIM / 4);   // float4 units

    const float4* y4p = reinterpret_cast<const float4*>(g_y) + base4;
    const float4* r4p = reinterpret_cast<const float4*>(raw) + base4;
    const float4* p4p = reinterpret_cast<const float4*>(protos) + (size_t)row * (NPROTO * DDIM / 4);
    const float4* bq4 = reinterpret_cast<const float4*>(bq);
    const float4* g4  = reinterpret_cast<const float4*>(gam);
    const float4* b4  = reinterpret_cast<const float4*>(bet);
    const float4* w4  = reinterpret_cast<const float4*>(Wg);

    // ---- LN1 input: y + bq ----
    float4 yv[4];
    float s0 = 0.f, s1 = 0.f;
    #pragma unroll
    for (int j = 0; j < 4; j++) {
        float4 v = y4p[lane + 32 * j];
        float4 b = bq4[lane + 32 * j];
        v.x += b.x; v.y += b.y; v.z += b.z; v.w += b.w;
        yv[j] = v;
        s0 += v.x + v.y + v.z + v.w;
        s1 += v.x*v.x + v.y*v.y + v.z*v.z + v.w*v.w;
    }
    s0 = wredsum(s0); s1 = wredsum(s1);
    float mean = s0 * (1.f / DDIM);
    float rstd = rsqrtf(s1 * (1.f / DDIM) - mean * mean + 1e-6f);

    // ---- q = tanh(LN(y)); |q|<=1 so the +-20 clip is a no-op ----
    float4 qv[4];
    float sqq = 0.f;
    #pragma unroll
    for (int j = 0; j < 4; j++) {
        float4 gm = g4[lane + 32 * j], bt = b4[lane + 32 * j];
        float4 q;
        q.x = tanhf((yv[j].x - mean) * rstd * gm.x + bt.x);
        q.y = tanhf((yv[j].y - mean) * rstd * gm.y + bt.y);
        q.z = tanhf((yv[j].z - mean) * rstd * gm.z + bt.z);
        q.w = tanhf((yv[j].w - mean) * rstd * gm.w + bt.w);
        qv[j] = q;
        sqq += q.x*q.x + q.y*q.y + q.z*q.z + q.w*q.w;
    }

    // ---- prototypes: |p_k|^2 and q.p_k, p kept in registers ----
    float4 pk[NPROTO][4];
    float spp[NPROTO], sqp[NPROTO];
    #pragma unroll
    for (int k = 0; k < NPROTO; k++) {
        float app = 0.f, aqp = 0.f;
        #pragma unroll
        for (int j = 0; j < 4; j++) {
            float4 v = p4p[k * (DDIM / 4) + lane + 32 * j];
            pk[k][j] = v;
            float4 c = c4(v, 20.f);
            app += c.x*c.x + c.y*c.y + c.z*c.z + c.w*c.w;
            aqp += qv[j].x*c.x + qv[j].y*c.y + qv[j].z*c.z + qv[j].w*c.w;
        }
        spp[k] = app; sqp[k] = aqp;
    }
    sqq = wredsum(sqq);
    #pragma unroll
    for (int k = 0; k < NPROTO; k++) { spp[k] = wredsum(spp[k]); sqp[k] = wredsum(sqp[k]); }

    // ---- cosine -> softmax (K=5, redundant per lane) ----
    float qn  = fmaxf(sqrtf(sqq), 1e-6f);
    float tmp = fminf(fmaxf(temperature[0], 0.5f), 5.f) + 1e-4f;
    float sim[NPROTO], mx = -1e30f;
    #pragma unroll
    for (int k = 0; k < NPROTO; k++) {
        float pn = fmaxf(sqrtf(spp[k]), 1e-6f);
        sim[k] = clampf(sqp[k] / (qn * pn), 15.f) / tmp;
        mx = fmaxf(mx, sim[k]);
    }
    float den = 0.f;
    #pragma unroll
    for (int k = 0; k < NPROTO; k++) { sim[k] = __expf(sim[k] - mx); den += sim[k]; }
    float inv = 1.f / den;
    #pragma unroll
    for (int k = 0; k < NPROTO; k++) sim[k] *= inv;

    // ---- cand + gate partial ----
    float4 cand[4], rw[4];
    float gs = 0.f;
    #pragma unroll
    for (int j = 0; j < 4; j++) {
        float4 c = make_float4(0.f, 0.f, 0.f, 0.f);
        #pragma unroll
        for (int k = 0; k < NPROTO; k++) {
            c.x += sim[k] * pk[k][j].x; c.y += sim[k] * pk[k][j].y;
            c.z += sim[k] * pk[k][j].z; c.w += sim[k] * pk[k][j].w;
        }
        c = c4(c, 5.f);
        cand[j] = c;
        float4 rv = c4(r4p[lane + 32 * j], 50.f);
        rw[j] = rv;
        float4 rc = c4(rv, 30.f);
        float4 wa = w4[lane + 32 * j];          // Wg[0:512]
        float4 wb = w4[128 + lane + 32 * j];    // Wg[512:1024]
        gs += wa.x*rc.x + wa.y*rc.y + wa.z*rc.z + wa.w*rc.w;
        gs += wb.x*c.x  + wb.y*c.y  + wb.z*c.z  + wb.w*c.w;
    }
    {   // time contribution: cols 0..127 live in j==0 slots
        float4 tv = c4(reinterpret_cast<const float4*>(te)[(size_t)row * (TDIM/4) + lane], 30.f);
        float4 wc = w4[256 + lane];             // Wg[1024:1152]
        gs += wc.x*tv.x + wc.y*tv.y + wc.z*tv.z + wc.w*tv.w;
    }
    gs = wredsum(gs);
    float logit = clampf(gs + bg[0], 10.f);
    float gg = 1.f / (1.f + __expf(-logit));

    // ---- blend + LN2 + clip ----
    float4 up[4];
    s0 = 0.f; s1 = 0.f;
    #pragma unroll
    for (int j = 0; j < 4; j++) {
        float4 u;
        u.x = 0.8f * rw[j].x + 0.2f * ((1.f - gg) * rw[j].x + gg * cand[j].x);
        u.y = 0.8f * rw[j].y + 0.2f * ((1.f - gg) * rw[j].y + gg * cand[j].y);
        u.z = 0.8f * rw[j].z + 0.2f * ((1.f - gg) * rw[j].z + gg * cand[j].z);
        u.w = 0.8f * rw[j].w + 0.2f * ((1.f - gg) * rw[j].w + gg * cand[j].w);
        up[j] = u;
        s0 += u.x + u.y + u.z + u.w;
        s1 += u.x*u.x + u.y*u.y + u.z*u.z + u.w*u.w;
    }
    s0 = wredsum(s0); s1 = wredsum(s1);
    mean = s0 * (1.f / DDIM);
    rstd = rsqrtf(s1 * (1.f / DDIM) - mean * mean + 1e-6f);
    float4* o4 = reinterpret_cast<float4*>(out) + base4;
    #pragma unroll
    for (int j = 0; j < 4; j++) {
        float4 gm = g4[lane + 32 * j], bt = b4[lane + 32 * j];
        float4 o;
        o.x = clampf((up[j].x - mean) * rstd * gm.x + bt.x, 10.f);
        o.y = clampf((up[j].y - mean) * rstd * gm.y + bt.y, 10.f);
        o.z = clampf((up[j].z - mean) * rstd * gm.z + bt.z, 10.f);
        o.w = clampf((up[j].w - mean) * rstd * gm.w + bt.w, 10.f);
        o4[lane + 32 * j] = o;
    }
}

// ---------------------------------------------------------------------------
extern "C" void kernel_launch(void* const* d_in, const int* in_sizes, int n_in,
                              void* d_out, int out_size) {
    (void)in_sizes; (void)n_in; (void)out_size;
    const float* raw  = (const float*)d_in[0];
    // d_in[1] = node_features: unused by the reference computation
    const float* edge = (const float*)d_in[2];
    const float* te   = (const float*)d_in[3];
    const float* prot = (const float*)d_in[4];
    const float* Wq   = (const float*)d_in[5];
    const float* bq   = (const float*)d_in[6];
    const float* Wg   = (const float*)d_in[7];
    const float* bg   = (const float*)d_in[8];
    const float* gam  = (const float*)d_in[9];
    const float* bet  = (const float*)d_in[10];
    const float* temp = (const float*)d_in[11];
    float* out = (float*)d_out;

    cudaFuncSetAttribute(gemm_kernel, cudaFuncAttributeMaxDynamicSharedMemorySize, SMEM_BYTES);
    gemm_kernel<<<dim3(4, 512), 256, SMEM_BYTES>>>(raw, edge, te, Wq);
    epilogue_kernel<<<NROWS / EPI_WARPS, EPI_WARPS * 32>>>(raw, te, prot, bq, Wg, bg, gam, bet, temp, out);
}

// round 12
// speedup vs baseline: 1.5162x; 1.5162x over previous
#include <cuda_runtime.h>
#include <cuda_bf16.h>
#include <cstdint>

#define NROWS 65536
#define DDIM  512
#define EDIM  256
#define TDIM  128
#define KDIM  896   // D + E + T
#define NPROTO 5

// Scratch (device globals per harness rules)
__device__ float g_y[(size_t)NROWS * DDIM];                       // GEMM out, 128 MB
__device__ __align__(16) __nv_bfloat16 g_B[(size_t)DDIM * KDIM];  // Wq in bf16, 0.9 MB

__device__ __forceinline__ uint32_t pack2(float a, float b) {
    __nv_bfloat162 h = __floats2bfloat162_rn(a, b);   // a -> low half
    return *reinterpret_cast<uint32_t*>(&h);
}

// ---------------------------------------------------------------------------
// Pre-convert Wq (fp32) -> g_B (bf16), row-major [512][896]
// ---------------------------------------------------------------------------
__global__ void convB_kernel(const float* __restrict__ Wq) {
    int i = blockIdx.x * 256 + threadIdx.x;           // 114688 float4 items
    float4 v = reinterpret_cast<const float4*>(Wq)[i];
    reinterpret_cast<uint2*>(g_B)[i] = make_uint2(pack2(v.x, v.y), pack2(v.z, v.w));
}

// ---------------------------------------------------------------------------
// GEMM: g_y[N,512] = concat(raw,edge,te)[N,896] @ Wq^T
//   bf16 smem (64B rows, XOR swizzle), B via cp.async from g_B,
//   A converted in-kernel (LDG fp32 -> bf16 STS), mma m16n8k16 bf16.
// ---------------------------------------------------------------------------
constexpr int BM = 128, BN = 128, BK = 32;
constexpr int TILE_B = BM * 64;               // 8 KB per tile (128 rows x 64 bytes)
constexpr int STAGEB = 2 * TILE_B;            // A + B per stage = 16 KB
// smem total: 2 stages = 32 KB (static)

__device__ __forceinline__ void cp16(uint32_t saddr, const void* gaddr) {
    asm volatile("cp.async.cg.shared.global [%0], [%1], 16;\n" :: "r"(saddr), "l"(gaddr));
}
// swizzled byte offset within a tile: row r (0..127), 16B-chunk c (0..3)
__device__ __forceinline__ int swz(int r, int c) {
    return r * 64 + ((c ^ ((r >> 1) & 3)) << 4);
}
// load one bf16x2 fragment word: row r, k-chunk c, lane tail t (k = 8c + 2t)
__device__ __forceinline__ uint32_t lds32(const char* base, int r, int c, int t) {
    return *reinterpret_cast<const uint32_t*>(base + swz(r, c) + 4 * t);
}

__global__ void __launch_bounds__(256, 2)
gemm_kernel(const float* __restrict__ raw, const float* __restrict__ edge,
            const float* __restrict__ te) {
    __shared__ char sm[2 * STAGEB];
    const int tid  = threadIdx.x;
    const int m0   = blockIdx.y * BM;
    const int n0   = blockIdx.x * BN;
    const int warp = tid >> 5, lane = tid & 31;
    const int wm   = warp & 3, wn = warp >> 2;   // 4 warps along M, 2 along N
    const int g    = lane >> 2, t = lane & 3;

    float acc[2][8][4];
    #pragma unroll
    for (int mi = 0; mi < 2; mi++)
        #pragma unroll
        for (int ni = 0; ni < 8; ni++)
            #pragma unroll
            for (int j = 0; j < 4; j++) acc[mi][ni][j] = 0.f;

    // ---- A source selection per k-chunk ----
    auto asrc = [&](int kt, const float*& base, int& stride, int& col0) {
        if (kt < 16)      { base = raw;  stride = DDIM; col0 = kt * 32; }
        else if (kt < 24) { base = edge; stride = EDIM; col0 = (kt - 16) * 32; }
        else              { base = te;   stride = TDIM; col0 = (kt - 24) * 32; }
    };
    // per-thread A fill coordinates: 4 items, item = tid + i*256 -> r=idx>>3, c4=idx&7
    float4 vA[4];
    auto ldgA = [&](int kt) {
        const float* base; int stride, col0;
        asrc(kt, base, stride, col0);
        #pragma unroll
        for (int i = 0; i < 4; i++) {
            int idx = tid + i * 256;
            int r = idx >> 3, c4 = idx & 7;
            vA[i] = *reinterpret_cast<const float4*>(
                base + (size_t)(m0 + r) * stride + col0 + c4 * 4);
        }
    };
    auto stsA = [&](char* As) {
        #pragma unroll
        for (int i = 0; i < 4; i++) {
            int idx = tid + i * 256;
            int r = idx >> 3, c4 = idx & 7;
            *reinterpret_cast<uint2*>(As + swz(r, c4 >> 1) + (c4 & 1) * 8) =
                make_uint2(pack2(vA[i].x, vA[i].y), pack2(vA[i].z, vA[i].w));
        }
    };
    auto cpB = [&](int kt, char* Bs) {
        const __nv_bfloat16* gb = g_B + (size_t)n0 * KDIM + kt * 32;
        #pragma unroll
        for (int i = 0; i < 2; i++) {
            int idx = tid + i * 256;            // 512 items: r = idx>>2, chunk = idx&3
            int r = idx >> 2, c = idx & 3;
            cp16((uint32_t)__cvta_generic_to_shared(Bs + swz(r, c)),
                 gb + (size_t)r * KDIM + c * 8);
        }
        asm volatile("cp.async.commit_group;\n");
    };

    // ---- prologue ----
    ldgA(0);
    stsA(sm);                 // A0 -> stage 0 (latency exposed once)
    cpB(0, sm + TILE_B);      // B0 -> stage 0 (group 0)
    ldgA(1);

    for (int kt = 0; kt < 28; kt++) {
        char* curA = sm + (kt & 1) * STAGEB;
        char* curB = curA + TILE_B;
        if (kt < 27) {
            char* nxtA = sm + ((kt + 1) & 1) * STAGEB;
            stsA(nxtA);                      // A(kt+1), loaded during kt-1
            cpB(kt + 1, nxtA + TILE_B);
            if (kt < 26) ldgA(kt + 2);       // hidden under compute(kt)
            asm volatile("cp.async.wait_group 1;\n");
        } else {
            asm volatile("cp.async.wait_group 0;\n");
        }
        __syncthreads();

        #pragma unroll
        for (int ks = 0; ks < 2; ks++) {     // two k16 steps per 32-chunk
            const int kc = ks * 2;           // k-chunk index (0 or 2)
            uint32_t a[2][4], b[8][2];
            #pragma unroll
            for (int mi = 0; mi < 2; mi++) {
                int r0 = wm * 32 + mi * 16 + g;
                a[mi][0] = lds32(curA, r0,     kc,     t);
                a[mi][1] = lds32(curA, r0 + 8, kc,     t);
                a[mi][2] = lds32(curA, r0,     kc + 1, t);
                a[mi][3] = lds32(curA, r0 + 8, kc + 1, t);
            }
            #pragma unroll
            for (int ni = 0; ni < 8; ni++) {
                int n = wn * 64 + ni * 8 + g;
                b[ni][0] = lds32(curB, n, kc,     t);
                b[ni][1] = lds32(curB, n, kc + 1, t);
            }
            #pragma unroll
            for (int mi = 0; mi < 2; mi++)
                #pragma unroll
                for (int ni = 0; ni < 8; ni++) {
                    float* c = acc[mi][ni];
                    asm volatile(
                        "mma.sync.aligned.m16n8k16.row.col.f32.bf16.bf16.f32 "
                        "{%0,%1,%2,%3}, {%4,%5,%6,%7}, {%8,%9}, {%0,%1,%2,%3};\n"
                        : "+f"(c[0]), "+f"(c[1]), "+f"(c[2]), "+f"(c[3])
                        : "r"(a[mi][0]), "r"(a[mi][1]), "r"(a[mi][2]), "r"(a[mi][3]),
                          "r"(b[ni][0]), "r"(b[ni][1]));
                }
        }
        __syncthreads();
    }

    // Writeback (c0,c1 adjacent columns -> float2)
    #pragma unroll
    for (int mi = 0; mi < 2; mi++) {
        int r0 = m0 + wm * 32 + mi * 16 + g;
        #pragma unroll
        for (int ni = 0; ni < 8; ni++) {
            int c = n0 + wn * 64 + ni * 8 + t * 2;
            *reinterpret_cast<float2*>(g_y + (size_t)r0 * DDIM + c) =
                make_float2(acc[mi][ni][0], acc[mi][ni][1]);
            *reinterpret_cast<float2*>(g_y + (size_t)(r0 + 8) * DDIM + c) =
                make_float2(acc[mi][ni][2], acc[mi][ni][3]);
        }
    }
}

// ---------------------------------------------------------------------------
// Fused epilogue: ONE WARP per row, zero __syncthreads (validated in R6).
// ---------------------------------------------------------------------------
__device__ __forceinline__ float wredsum(float x) {
    #pragma unroll
    for (int o = 16; o > 0; o >>= 1) x += __shfl_xor_sync(0xffffffffu, x, o);
    return x;
}
__device__ __forceinline__ float clampf(float x, float a) { return fminf(fmaxf(x, -a), a); }
__device__ __forceinline__ float4 c4(float4 v, float a) {
    return make_float4(clampf(v.x,a), clampf(v.y,a), clampf(v.z,a), clampf(v.w,a));
}

constexpr int EPI_WARPS = 4;   // rows per block

__global__ void __launch_bounds__(EPI_WARPS * 32)
epilogue_kernel(const float* __restrict__ raw, const float* __restrict__ te,
                const float* __restrict__ protos, const float* __restrict__ bq,
                const float* __restrict__ Wg, const float* __restrict__ bg,
                const float* __restrict__ gam, const float* __restrict__ bet,
                const float* __restrict__ temperature, float* __restrict__ out) {
    const int lane = threadIdx.x & 31;
    const int row  = blockIdx.x * EPI_WARPS + (threadIdx.x >> 5);
    const size_t base4 = (size_t)row * (DDIM / 4);   // float4 units

    const float4* y4p = reinterpret_cast<const float4*>(g_y) + base4;
    const float4* r4p = reinterpret_cast<const float4*>(raw) + base4;
    const float4* p4p = reinterpret_cast<const float4*>(protos) + (size_t)row * (NPROTO * DDIM / 4);
    const float4* bq4 = reinterpret_cast<const float4*>(bq);
    const float4* g4  = reinterpret_cast<const float4*>(gam);
    const float4* b4  = reinterpret_cast<const float4*>(bet);
    const float4* w4  = reinterpret_cast<const float4*>(Wg);

    // ---- LN1 input: y + bq ----
    float4 yv[4];
    float s0 = 0.f, s1 = 0.f;
    #pragma unroll
    for (int j = 0; j < 4; j++) {
        float4 v = y4p[lane + 32 * j];
        float4 b = bq4[lane + 32 * j];
        v.x += b.x; v.y += b.y; v.z += b.z; v.w += b.w;
        yv[j] = v;
        s0 += v.x + v.y + v.z + v.w;
        s1 += v.x*v.x + v.y*v.y + v.z*v.z + v.w*v.w;
    }
    s0 = wredsum(s0); s1 = wredsum(s1);
    float mean = s0 * (1.f / DDIM);
    float rstd = rsqrtf(s1 * (1.f / DDIM) - mean * mean + 1e-6f);

    // ---- q = tanh(LN(y)); |q|<=1 so the +-20 clip is a no-op ----
    float4 qv[4];
    float sqq = 0.f;
    #pragma unroll
    for (int j = 0; j < 4; j++) {
        float4 gm = g4[lane + 32 * j], bt = b4[lane + 32 * j];
        float4 q;
        q.x = tanhf((yv[j].x - mean) * rstd * gm.x + bt.x);
        q.y = tanhf((yv[j].y - mean) * rstd * gm.y + bt.y);
        q.z = tanhf((yv[j].z - mean) * rstd * gm.z + bt.z);
        q.w = tanhf((yv[j].w - mean) * rstd * gm.w + bt.w);
        qv[j] = q;
        sqq += q.x*q.x + q.y*q.y + q.z*q.z + q.w*q.w;
    }

    // ---- prototypes: |p_k|^2 and q.p_k, p kept in registers ----
    float4 pk[NPROTO][4];
    float spp[NPROTO], sqp[NPROTO];
    #pragma unroll
    for (int k = 0; k < NPROTO; k++) {
        float app = 0.f, aqp = 0.f;
        #pragma unroll
        for (int j = 0; j < 4; j++) {
            float4 v = p4p[k * (DDIM / 4) + lane + 32 * j];
            pk[k][j] = v;
            float4 c = c4(v, 20.f);
            app += c.x*c.x + c.y*c.y + c.z*c.z + c.w*c.w;
            aqp += qv[j].x*c.x + qv[j].y*c.y + qv[j].z*c.z + qv[j].w*c.w;
        }
        spp[k] = app; sqp[k] = aqp;
    }
    sqq = wredsum(sqq);
    #pragma unroll
    for (int k = 0; k < NPROTO; k++) { spp[k] = wredsum(spp[k]); sqp[k] = wredsum(sqp[k]); }

    // ---- cosine -> softmax (K=5, redundant per lane) ----
    float qn  = fmaxf(sqrtf(sqq), 1e-6f);
    float tmp = fminf(fmaxf(temperature[0], 0.5f), 5.f) + 1e-4f;
    float sim[NPROTO], mx = -1e30f;
    #pragma unroll
    for (int k = 0; k < NPROTO; k++) {
        float pn = fmaxf(sqrtf(spp[k]), 1e-6f);
        sim[k] = clampf(sqp[k] / (qn * pn), 15.f) / tmp;
        mx = fmaxf(mx, sim[k]);
    }
    float den = 0.f;
    #pragma unroll
    for (int k = 0; k < NPROTO; k++) { sim[k] = __expf(sim[k] - mx); den += sim[k]; }
    float inv = 1.f / den;
    #pragma unroll
    for (int k = 0; k < NPROTO; k++) sim[k] *= inv;

    // ---- cand + gate partial ----
    float4 cand[4], rw[4];
    float gs = 0.f;
    #pragma unroll
    for (int j = 0; j < 4; j++) {
        float4 c = make_float4(0.f, 0.f, 0.f, 0.f);
        #pragma unroll
        for (int k = 0; k < NPROTO; k++) {
            c.x += sim[k] * pk[k][j].x; c.y += sim[k] * pk[k][j].y;
            c.z += sim[k] * pk[k][j].z; c.w += sim[k] * pk[k][j].w;
        }
        c = c4(c, 5.f);
        cand[j] = c;
        float4 rv = c4(r4p[lane + 32 * j], 50.f);
        rw[j] = rv;
        float4 rc = c4(rv, 30.f);
        float4 wa = w4[lane + 32 * j];          // Wg[0:512]
        float4 wb = w4[128 + lane + 32 * j];    // Wg[512:1024]
        gs += wa.x*rc.x + wa.y*rc.y + wa.z*rc.z + wa.w*rc.w;
        gs += wb.x*c.x  + wb.y*c.y  + wb.z*c.z  + wb.w*c.w;
    }
    {   // time contribution: cols 0..127 live in j==0 slots
        float4 tv = c4(reinterpret_cast<const float4*>(te)[(size_t)row * (TDIM/4) + lane], 30.f);
        float4 wc = w4[256 + lane];             // Wg[1024:1152]
        gs += wc.x*tv.x + wc.y*tv.y + wc.z*tv.z + wc.w*tv.w;
    }
    gs = wredsum(gs);
    float logit = clampf(gs + bg[0], 10.f);
    float gg = 1.f / (1.f + __expf(-logit));

    // ---- blend + LN2 + clip ----
    float4 up[4];
    s0 = 0.f; s1 = 0.f;
    #pragma unroll
    for (int j = 0; j < 4; j++) {
        float4 u;
        u.x = 0.8f * rw[j].x + 0.2f * ((1.f - gg) * rw[j].x + gg * cand[j].x);
        u.y = 0.8f * rw[j].y + 0.2f * ((1.f - gg) * rw[j].y + gg * cand[j].y);
        u.z = 0.8f * rw[j].z + 0.2f * ((1.f - gg) * rw[j].z + gg * cand[j].z);
        u.w = 0.8f * rw[j].w + 0.2f * ((1.f - gg) * rw[j].w + gg * cand[j].w);
        up[j] = u;
        s0 += u.x + u.y + u.z + u.w;
        s1 += u.x*u.x + u.y*u.y + u.z*u.z + u.w*u.w;
    }
    s0 = wredsum(s0); s1 = wredsum(s1);
    mean = s0 * (1.f / DDIM);
    rstd = rsqrtf(s1 * (1.f / DDIM) - mean * mean + 1e-6f);
    float4* o4 = reinterpret_cast<float4*>(out) + base4;
    #pragma unroll
    for (int j = 0; j < 4; j++) {
        float4 gm = g4[lane + 32 * j], bt = b4[lane + 32 * j];
        float4 o;
        o.x = clampf((up[j].x - mean) * rstd * gm.x + bt.x, 10.f);
        o.y = clampf((up[j].y - mean) * rstd * gm.y + bt.y, 10.f);
        o.z = clampf((up[j].z - mean) * rstd * gm.z + bt.z, 10.f);
        o.w = clampf((up[j].w - mean) * rstd * gm.w + bt.w, 10.f);
        o4[lane + 32 * j] = o;
    }
}

// ---------------------------------------------------------------------------
extern "C" void kernel_launch(void* const* d_in, const int* in_sizes, int n_in,
                              void* d_out, int out_size) {
    (void)in_sizes; (void)n_in; (void)out_size;
    const float* raw  = (const float*)d_in[0];
    // d_in[1] = node_features: unused by the reference computation
    const float* edge = (const float*)d_in[2];
    const float* te   = (const float*)d_in[3];
    const float* prot = (const float*)d_in[4];
    const float* Wq   = (const float*)d_in[5];
    const float* bq   = (const float*)d_in[6];
    const float* Wg   = (const float*)d_in[7];
    const float* bg   = (const float*)d_in[8];
    const float* gam  = (const float*)d_in[9];
    const float* bet  = (const float*)d_in[10];
    const float* temp = (const float*)d_in[11];
    float* out = (float*)d_out;

    convB_kernel<<<(DDIM * KDIM / 4) / 256, 256>>>(Wq);
    gemm_kernel<<<dim3(4, 512), 256>>>(raw, edge, te);
    epilogue_kernel<<<NROWS / EPI_WARPS, EPI_WARPS * 32>>>(raw, te, prot, bq, Wg, bg, gam, bet, temp, out);
}

// round 13
// speedup vs baseline: 1.5568x; 1.0267x over previous
#include <cuda_runtime.h>
#include <cuda_bf16.h>
#include <cstdint>

#define NROWS 65536
#define DDIM  512
#define EDIM  256
#define TDIM  128
#define KDIM  896   // D + E + T
#define NPROTO 5

// Scratch (device globals per harness rules)
__device__ float g_y[(size_t)NROWS * DDIM];                       // GEMM out, 128 MB
__device__ __align__(16) __nv_bfloat16 g_B[(size_t)DDIM * KDIM];  // Wq in bf16, 0.9 MB

__device__ __forceinline__ uint32_t pack2(float a, float b) {
    __nv_bfloat162 h = __floats2bfloat162_rn(a, b);   // a -> low half
    return *reinterpret_cast<uint32_t*>(&h);
}

// ---------------------------------------------------------------------------
// Pre-convert Wq (fp32) -> g_B (bf16), row-major [512][896]
// ---------------------------------------------------------------------------
__global__ void convB_kernel(const float* __restrict__ Wq) {
    int i = blockIdx.x * 256 + threadIdx.x;           // 114688 float4 items
    float4 v = reinterpret_cast<const float4*>(Wq)[i];
    reinterpret_cast<uint2*>(g_B)[i] = make_uint2(pack2(v.x, v.y), pack2(v.z, v.w));
}

// ---------------------------------------------------------------------------
// GEMM: g_y[N,512] = concat(raw,edge,te)[N,896] @ Wq^T
//   BM=128, BN=256 (A read only 2x from DRAM), bf16 smem, occ 1.
//   Warp layout: 2 warps along M (64 rows), 4 along N (64 cols).
// ---------------------------------------------------------------------------
constexpr int BM = 128, BN = 256;
constexpr int A_TILE = BM * 64;               // 8 KB  (128 rows x 64 B)
constexpr int B_TILE = BN * 64;               // 16 KB (256 rows x 64 B)
constexpr int STAGEB = A_TILE + B_TILE;       // 24 KB per stage

__device__ __forceinline__ void cp16(uint32_t saddr, const void* gaddr) {
    asm volatile("cp.async.cg.shared.global [%0], [%1], 16;\n" :: "r"(saddr), "l"(gaddr));
}
// swizzled byte offset within a tile: row r, 16B-chunk c (0..3)
__device__ __forceinline__ int swz(int r, int c) {
    return r * 64 + ((c ^ ((r >> 1) & 3)) << 4);
}
__device__ __forceinline__ uint32_t lds32(const char* base, int r, int c, int t) {
    return *reinterpret_cast<const uint32_t*>(base + swz(r, c) + 4 * t);
}

__global__ void __launch_bounds__(256, 1)
gemm_kernel(const float* __restrict__ raw, const float* __restrict__ edge,
            const float* __restrict__ te) {
    __shared__ char sm[2 * STAGEB];
    const int tid  = threadIdx.x;
    const int m0   = blockIdx.y * BM;
    const int n0   = blockIdx.x * BN;
    const int warp = tid >> 5, lane = tid & 31;
    const int wm   = warp & 1, wn = warp >> 1;   // 2 warps along M, 4 along N
    const int g    = lane >> 2, t = lane & 3;

    float acc[4][8][4];
    #pragma unroll
    for (int mi = 0; mi < 4; mi++)
        #pragma unroll
        for (int ni = 0; ni < 8; ni++)
            #pragma unroll
            for (int j = 0; j < 4; j++) acc[mi][ni][j] = 0.f;

    auto asrc = [&](int kt, const float*& base, int& stride, int& col0) {
        if (kt < 16)      { base = raw;  stride = DDIM; col0 = kt * 32; }
        else if (kt < 24) { base = edge; stride = EDIM; col0 = (kt - 16) * 32; }
        else              { base = te;   stride = TDIM; col0 = (kt - 24) * 32; }
    };
    float4 vA[4];
    auto ldgA = [&](int kt) {
        const float* base; int stride, col0;
        asrc(kt, base, stride, col0);
        #pragma unroll
        for (int i = 0; i < 4; i++) {
            int idx = tid + i * 256;
            int r = idx >> 3, c4 = idx & 7;
            vA[i] = *reinterpret_cast<const float4*>(
                base + (size_t)(m0 + r) * stride + col0 + c4 * 4);
        }
    };
    auto stsA = [&](char* As) {
        #pragma unroll
        for (int i = 0; i < 4; i++) {
            int idx = tid + i * 256;
            int r = idx >> 3, c4 = idx & 7;
            *reinterpret_cast<uint2*>(As + swz(r, c4 >> 1) + (c4 & 1) * 8) =
                make_uint2(pack2(vA[i].x, vA[i].y), pack2(vA[i].z, vA[i].w));
        }
    };
    auto cpB = [&](int kt, char* Bs) {
        const __nv_bfloat16* gb = g_B + (size_t)n0 * KDIM + kt * 32;
        #pragma unroll
        for (int i = 0; i < 4; i++) {
            int idx = tid + i * 256;            // 1024 items: r = idx>>2, chunk = idx&3
            int r = idx >> 2, c = idx & 3;
            cp16((uint32_t)__cvta_generic_to_shared(Bs + swz(r, c)),
                 gb + (size_t)r * KDIM + c * 8);
        }
        asm volatile("cp.async.commit_group;\n");
    };

    // ---- prologue ----
    ldgA(0);
    stsA(sm);                 // A0 -> stage 0
    cpB(0, sm + A_TILE);      // B0 -> stage 0
    ldgA(1);

    for (int kt = 0; kt < 28; kt++) {
        char* curA = sm + (kt & 1) * STAGEB;
        char* curB = curA + A_TILE;
        if (kt < 27) {
            char* nxtA = sm + ((kt + 1) & 1) * STAGEB;
            stsA(nxtA);                      // A(kt+1), loaded at kt-1
            cpB(kt + 1, nxtA + A_TILE);
            if (kt < 26) ldgA(kt + 2);       // hidden under compute(kt)
            asm volatile("cp.async.wait_group 1;\n");
        } else {
            asm volatile("cp.async.wait_group 0;\n");
        }
        __syncthreads();

        #pragma unroll
        for (int ks = 0; ks < 2; ks++) {     // two k16 steps per 32-chunk
            const int kc = ks * 2;
            uint32_t a[4][4], b[8][2];
            #pragma unroll
            for (int mi = 0; mi < 4; mi++) {
                int r0 = wm * 64 + mi * 16 + g;
                a[mi][0] = lds32(curA, r0,     kc,     t);
                a[mi][1] = lds32(curA, r0 + 8, kc,     t);
                a[mi][2] = lds32(curA, r0,     kc + 1, t);
                a[mi][3] = lds32(curA, r0 + 8, kc + 1, t);
            }
            #pragma unroll
            for (int ni = 0; ni < 8; ni++) {
                int n = wn * 64 + ni * 8 + g;
                b[ni][0] = lds32(curB, n, kc,     t);
                b[ni][1] = lds32(curB, n, kc + 1, t);
            }
            #pragma unroll
            for (int mi = 0; mi < 4; mi++)
                #pragma unroll
                for (int ni = 0; ni < 8; ni++) {
                    float* c = acc[mi][ni];
                    asm volatile(
                        "mma.sync.aligned.m16n8k16.row.col.f32.bf16.bf16.f32 "
                        "{%0,%1,%2,%3}, {%4,%5,%6,%7}, {%8,%9}, {%0,%1,%2,%3};\n"
                        : "+f"(c[0]), "+f"(c[1]), "+f"(c[2]), "+f"(c[3])
                        : "r"(a[mi][0]), "r"(a[mi][1]), "r"(a[mi][2]), "r"(a[mi][3]),
                          "r"(b[ni][0]), "r"(b[ni][1]));
                }
        }
        __syncthreads();
    }

    // Writeback (c0,c1 adjacent columns -> float2)
    #pragma unroll
    for (int mi = 0; mi < 4; mi++) {
        int r0 = m0 + wm * 64 + mi * 16 + g;
        #pragma unroll
        for (int ni = 0; ni < 8; ni++) {
            int c = n0 + wn * 64 + ni * 8 + t * 2;
            *reinterpret_cast<float2*>(g_y + (size_t)r0 * DDIM + c) =
                make_float2(acc[mi][ni][0], acc[mi][ni][1]);
            *reinterpret_cast<float2*>(g_y + (size_t)(r0 + 8) * DDIM + c) =
                make_float2(acc[mi][ni][2], acc[mi][ni][3]);
        }
    }
}

// ---------------------------------------------------------------------------
// Fused epilogue: ONE WARP per row, zero __syncthreads (validated in R6).
// ---------------------------------------------------------------------------
__device__ __forceinline__ float wredsum(float x) {
    #pragma unroll
    for (int o = 16; o > 0; o >>= 1) x += __shfl_xor_sync(0xffffffffu, x, o);
    return x;
}
__device__ __forceinline__ float clampf(float x, float a) { return fminf(fmaxf(x, -a), a); }
__device__ __forceinline__ float4 c4(float4 v, float a) {
    return make_float4(clampf(v.x,a), clampf(v.y,a), clampf(v.z,a), clampf(v.w,a));
}

constexpr int EPI_WARPS = 4;   // rows per block

__global__ void __launch_bounds__(EPI_WARPS * 32)
epilogue_kernel(const float* __restrict__ raw, const float* __restrict__ te,
                const float* __restrict__ protos, const float* __restrict__ bq,
                const float* __restrict__ Wg, const float* __restrict__ bg,
                const float* __restrict__ gam, const float* __restrict__ bet,
                const float* __restrict__ temperature, float* __restrict__ out) {
    const int lane = threadIdx.x & 31;
    const int row  = blockIdx.x * EPI_WARPS + (threadIdx.x >> 5);
    const size_t base4 = (size_t)row * (DDIM / 4);   // float4 units

    const float4* y4p = reinterpret_cast<const float4*>(g_y) + base4;
    const float4* r4p = reinterpret_cast<const float4*>(raw) + base4;
    const float4* p4p = reinterpret_cast<const float4*>(protos) + (size_t)row * (NPROTO * DDIM / 4);
    const float4* bq4 = reinterpret_cast<const float4*>(bq);
    const float4* g4  = reinterpret_cast<const float4*>(gam);
    const float4* b4  = reinterpret_cast<const float4*>(bet);
    const float4* w4  = reinterpret_cast<const float4*>(Wg);

    // ---- LN1 input: y + bq ----
    float4 yv[4];
    float s0 = 0.f, s1 = 0.f;
    #pragma unroll
    for (int j = 0; j < 4; j++) {
        float4 v = y4p[lane + 32 * j];
        float4 b = bq4[lane + 32 * j];
        v.x += b.x; v.y += b.y; v.z += b.z; v.w += b.w;
        yv[j] = v;
        s0 += v.x + v.y + v.z + v.w;
        s1 += v.x*v.x + v.y*v.y + v.z*v.z + v.w*v.w;
    }
    s0 = wredsum(s0); s1 = wredsum(s1);
    float mean = s0 * (1.f / DDIM);
    float rstd = rsqrtf(s1 * (1.f / DDIM) - mean * mean + 1e-6f);

    // ---- q = tanh(LN(y)); |q|<=1 so the +-20 clip is a no-op ----
    float4 qv[4];
    float sqq = 0.f;
    #pragma unroll
    for (int j = 0; j < 4; j++) {
        float4 gm = g4[lane + 32 * j], bt = b4[lane + 32 * j];
        float4 q;
        q.x = tanhf((yv[j].x - mean) * rstd * gm.x + bt.x);
        q.y = tanhf((yv[j].y - mean) * rstd * gm.y + bt.y);
        q.z = tanhf((yv[j].z - mean) * rstd * gm.z + bt.z);
        q.w = tanhf((yv[j].w - mean) * rstd * gm.w + bt.w);
        qv[j] = q;
        sqq += q.x*q.x + q.y*q.y + q.z*q.z + q.w*q.w;
    }

    // ---- prototypes: |p_k|^2 and q.p_k, p kept in registers ----
    float4 pk[NPROTO][4];
    float spp[NPROTO], sqp[NPROTO];
    #pragma unroll
    for (int k = 0; k < NPROTO; k++) {
        float app = 0.f, aqp = 0.f;
        #pragma unroll
        for (int j = 0; j < 4; j++) {
            float4 v = p4p[k * (DDIM / 4) + lane + 32 * j];
            pk[k][j] = v;
            float4 c = c4(v, 20.f);
            app += c.x*c.x + c.y*c.y + c.z*c.z + c.w*c.w;
            aqp += qv[j].x*c.x + qv[j].y*c.y + qv[j].z*c.z + qv[j].w*c.w;
        }
        spp[k] = app; sqp[k] = aqp;
    }
    sqq = wredsum(sqq);
    #pragma unroll
    for (int k = 0; k < NPROTO; k++) { spp[k] = wredsum(spp[k]); sqp[k] = wredsum(sqp[k]); }

    // ---- cosine -> softmax (K=5, redundant per lane) ----
    float qn  = fmaxf(sqrtf(sqq), 1e-6f);
    float tmp = fminf(fmaxf(temperature[0], 0.5f), 5.f) + 1e-4f;
    float sim[NPROTO], mx = -1e30f;
    #pragma unroll
    for (int k = 0; k < NPROTO; k++) {
        float pn = fmaxf(sqrtf(spp[k]), 1e-6f);
        sim[k] = clampf(sqp[k] / (qn * pn), 15.f) / tmp;
        mx = fmaxf(mx, sim[k]);
    }
    float den = 0.f;
    #pragma unroll
    for (int k = 0; k < NPROTO; k++) { sim[k] = __expf(sim[k] - mx); den += sim[k]; }
    float inv = 1.f / den;
    #pragma unroll
    for (int k = 0; k < NPROTO; k++) sim[k] *= inv;

    // ---- cand + gate partial ----
    float4 cand[4], rw[4];
    float gs = 0.f;
    #pragma unroll
    for (int j = 0; j < 4; j++) {
        float4 c = make_float4(0.f, 0.f, 0.f, 0.f);
        #pragma unroll
        for (int k = 0; k < NPROTO; k++) {
            c.x += sim[k] * pk[k][j].x; c.y += sim[k] * pk[k][j].y;
            c.z += sim[k] * pk[k][j].z; c.w += sim[k] * pk[k][j].w;
        }
        c = c4(c, 5.f);
        cand[j] = c;
        float4 rv = c4(r4p[lane + 32 * j], 50.f);
        rw[j] = rv;
        float4 rc = c4(rv, 30.f);
        float4 wa = w4[lane + 32 * j];          // Wg[0:512]
        float4 wb = w4[128 + lane + 32 * j];    // Wg[512:1024]
        gs += wa.x*rc.x + wa.y*rc.y + wa.z*rc.z + wa.w*rc.w;
        gs += wb.x*c.x  + wb.y*c.y  + wb.z*c.z  + wb.w*c.w;
    }
    {   // time contribution: cols 0..127 live in j==0 slots
        float4 tv = c4(reinterpret_cast<const float4*>(te)[(size_t)row * (TDIM/4) + lane], 30.f);
        float4 wc = w4[256 + lane];             // Wg[1024:1152]
        gs += wc.x*tv.x + wc.y*tv.y + wc.z*tv.z + wc.w*tv.w;
    }
    gs = wredsum(gs);
    float logit = clampf(gs + bg[0], 10.f);
    float gg = 1.f / (1.f + __expf(-logit));

    // ---- blend + LN2 + clip ----
    float4 up[4];
    s0 = 0.f; s1 = 0.f;
    #pragma unroll
    for (int j = 0; j < 4; j++) {
        float4 u;
        u.x = 0.8f * rw[j].x + 0.2f * ((1.f - gg) * rw[j].x + gg * cand[j].x);
        u.y = 0.8f * rw[j].y + 0.2f * ((1.f - gg) * rw[j].y + gg * cand[j].y);
        u.z = 0.8f * rw[j].z + 0.2f * ((1.f - gg) * rw[j].z + gg * cand[j].z);
        u.w = 0.8f * rw[j].w + 0.2f * ((1.f - gg) * rw[j].w + gg * cand[j].w);
        up[j] = u;
        s0 += u.x + u.y + u.z + u.w;
        s1 += u.x*u.x + u.y*u.y + u.z*u.z + u.w*u.w;
    }
    s0 = wredsum(s0); s1 = wredsum(s1);
    mean = s0 * (1.f / DDIM);
    rstd = rsqrtf(s1 * (1.f / DDIM) - mean * mean + 1e-6f);
    float4* o4 = reinterpret_cast<float4*>(out) + base4;
    #pragma unroll
    for (int j = 0; j < 4; j++) {
        float4 gm = g4[lane + 32 * j], bt = b4[lane + 32 * j];
        float4 o;
        o.x = clampf((up[j].x - mean) * rstd * gm.x + bt.x, 10.f);
        o.y = clampf((up[j].y - mean) * rstd * gm.y + bt.y, 10.f);
        o.z = clampf((up[j].z - mean) * rstd * gm.z + bt.z, 10.f);
        o.w = clampf((up[j].w - mean) * rstd * gm.w + bt.w, 10.f);
        o4[lane + 32 * j] = o;
    }
}

// ---------------------------------------------------------------------------
extern "C" void kernel_launch(void* const* d_in, const int* in_sizes, int n_in,
                              void* d_out, int out_size) {
    (void)in_sizes; (void)n_in; (void)out_size;
    const float* raw  = (const float*)d_in[0];
    // d_in[1] = node_features: unused by the reference computation
    const float* edge = (const float*)d_in[2];
    const float* te   = (const float*)d_in[3];
    const float* prot = (const float*)d_in[4];
    const float* Wq   = (const float*)d_in[5];
    const float* bq   = (const float*)d_in[6];
    const float* Wg   = (const float*)d_in[7];
    const float* bg   = (const float*)d_in[8];
    const float* gam  = (const float*)d_in[9];
    const float* bet  = (const float*)d_in[10];
    const float* temp = (const float*)d_in[11];
    float* out = (float*)d_out;

    convB_kernel<<<(DDIM * KDIM / 4) / 256, 256>>>(Wq);
    gemm_kernel<<<dim3(2, 512), 256>>>(raw, edge, te);
    epilogue_kernel<<<NROWS / EPI_WARPS, EPI_WARPS * 32>>>(raw, te, prot, bq, Wg, bg, gam, bet, temp, out);
}

// round 15
// speedup vs baseline: 1.6077x; 1.0327x over previous
#include <cuda_runtime.h>
#include <cuda_bf16.h>
#include <cstdint>

#define NROWS 65536
#define DDIM  512
#define EDIM  256
#define TDIM  128
#define KDIM  896   // D + E + T
#define NPROTO 5

// Scratch (device globals per harness rules)
__device__ __align__(16) __nv_bfloat16 g_y[(size_t)NROWS * DDIM]; // GEMM out, 64 MB (bf16)
__device__ __align__(16) __nv_bfloat16 g_B[(size_t)DDIM * KDIM];  // Wq in bf16, 0.9 MB

__device__ __forceinline__ uint32_t pack2(float a, float b) {
    __nv_bfloat162 h = __floats2bfloat162_rn(a, b);   // a -> low half
    return *reinterpret_cast<uint32_t*>(&h);
}
__device__ __forceinline__ float2 unpack2(uint32_t u) {
    return __bfloat1622float2(*reinterpret_cast<__nv_bfloat162*>(&u));
}

// ---------------------------------------------------------------------------
// Pre-convert Wq (fp32) -> g_B (bf16), row-major [512][896]
// ---------------------------------------------------------------------------
__global__ void convB_kernel(const float* __restrict__ Wq) {
    int i = blockIdx.x * 256 + threadIdx.x;           // 114688 float4 items
    float4 v = reinterpret_cast<const float4*>(Wq)[i];
    reinterpret_cast<uint2*>(g_B)[i] = make_uint2(pack2(v.x, v.y), pack2(v.z, v.w));
}

// ---------------------------------------------------------------------------
// GEMM: g_y[N,512] = concat(raw,edge,te)[N,896] @ Wq^T  (bf16 out)
//   BM=128, BN=256, bf16 smem, occ 1. Tensor-pipe saturated (~546 MAC/cyc/SM).
// ---------------------------------------------------------------------------
constexpr int BM = 128, BN = 256;
constexpr int A_TILE = BM * 64;               // 8 KB
constexpr int B_TILE = BN * 64;               // 16 KB
constexpr int STAGEB = A_TILE + B_TILE;       // 24 KB per stage

__device__ __forceinline__ void cp16(uint32_t saddr, const void* gaddr) {
    asm volatile("cp.async.cg.shared.global [%0], [%1], 16;\n" :: "r"(saddr), "l"(gaddr));
}
__device__ __forceinline__ int swz(int r, int c) {
    return r * 64 + ((c ^ ((r >> 1) & 3)) << 4);
}
__device__ __forceinline__ uint32_t lds32(const char* base, int r, int c, int t) {
    return *reinterpret_cast<const uint32_t*>(base + swz(r, c) + 4 * t);
}

__global__ void __launch_bounds__(256, 1)
gemm_kernel(const float* __restrict__ raw, const float* __restrict__ edge,
            const float* __restrict__ te) {
    __shared__ char sm[2 * STAGEB];
    const int tid  = threadIdx.x;
    const int m0   = blockIdx.y * BM;
    const int n0   = blockIdx.x * BN;
    const int warp = tid >> 5, lane = tid & 31;
    const int wm   = warp & 1, wn = warp >> 1;   // 2 warps along M, 4 along N
    const int g    = lane >> 2, t = lane & 3;

    float acc[4][8][4];
    #pragma unroll
    for (int mi = 0; mi < 4; mi++)
        #pragma unroll
        for (int ni = 0; ni < 8; ni++)
            #pragma unroll
            for (int j = 0; j < 4; j++) acc[mi][ni][j] = 0.f;

    auto asrc = [&](int kt, const float*& base, int& stride, int& col0) {
        if (kt < 16)      { base = raw;  stride = DDIM; col0 = kt * 32; }
        else if (kt < 24) { base = edge; stride = EDIM; col0 = (kt - 16) * 32; }
        else              { base = te;   stride = TDIM; col0 = (kt - 24) * 32; }
    };
    float4 vA[4];
    auto ldgA = [&](int kt) {
        const float* base; int stride, col0;
        asrc(kt, base, stride, col0);
        #pragma unroll
        for (int i = 0; i < 4; i++) {
            int idx = tid + i * 256;
            int r = idx >> 3, c4 = idx & 7;
            vA[i] = *reinterpret_cast<const float4*>(
                base + (size_t)(m0 + r) * stride + col0 + c4 * 4);
        }
    };
    auto stsA = [&](char* As) {
        #pragma unroll
        for (int i = 0; i < 4; i++) {
            int idx = tid + i * 256;
            int r = idx >> 3, c4 = idx & 7;
            *reinterpret_cast<uint2*>(As + swz(r, c4 >> 1) + (c4 & 1) * 8) =
                make_uint2(pack2(vA[i].x, vA[i].y), pack2(vA[i].z, vA[i].w));
        }
    };
    auto cpB = [&](int kt, char* Bs) {
        const __nv_bfloat16* gb = g_B + (size_t)n0 * KDIM + kt * 32;
        #pragma unroll
        for (int i = 0; i < 4; i++) {
            int idx = tid + i * 256;
            int r = idx >> 2, c = idx & 3;
            cp16((uint32_t)__cvta_generic_to_shared(Bs + swz(r, c)),
                 gb + (size_t)r * KDIM + c * 8);
        }
        asm volatile("cp.async.commit_group;\n");
    };

    // ---- prologue ----
    ldgA(0);
    stsA(sm);
    cpB(0, sm + A_TILE);
    ldgA(1);

    for (int kt = 0; kt < 28; kt++) {
        char* curA = sm + (kt & 1) * STAGEB;
        char* curB = curA + A_TILE;
        if (kt < 27) {
            char* nxtA = sm + ((kt + 1) & 1) * STAGEB;
            stsA(nxtA);
            cpB(kt + 1, nxtA + A_TILE);
            if (kt < 26) ldgA(kt + 2);
            asm volatile("cp.async.wait_group 1;\n");
        } else {
            asm volatile("cp.async.wait_group 0;\n");
        }
        __syncthreads();

        #pragma unroll
        for (int ks = 0; ks < 2; ks++) {
            const int kc = ks * 2;
            uint32_t a[4][4], b[8][2];
            #pragma unroll
            for (int mi = 0; mi < 4; mi++) {
                int r0 = wm * 64 + mi * 16 + g;
                a[mi][0] = lds32(curA, r0,     kc,     t);
                a[mi][1] = lds32(curA, r0 + 8, kc,     t);
                a[mi][2] = lds32(curA, r0,     kc + 1, t);
                a[mi][3] = lds32(curA, r0 + 8, kc + 1, t);
            }
            #pragma unroll
            for (int ni = 0; ni < 8; ni++) {
                int n = wn * 64 + ni * 8 + g;
                b[ni][0] = lds32(curB, n, kc,     t);
                b[ni][1] = lds32(curB, n, kc + 1, t);
            }
            #pragma unroll
            for (int mi = 0; mi < 4; mi++)
                #pragma unroll
                for (int ni = 0; ni < 8; ni++) {
                    float* c = acc[mi][ni];
                    asm volatile(
                        "mma.sync.aligned.m16n8k16.row.col.f32.bf16.bf16.f32 "
                        "{%0,%1,%2,%3}, {%4,%5,%6,%7}, {%8,%9}, {%0,%1,%2,%3};\n"
                        : "+f"(c[0]), "+f"(c[1]), "+f"(c[2]), "+f"(c[3])
                        : "r"(a[mi][0]), "r"(a[mi][1]), "r"(a[mi][2]), "r"(a[mi][3]),
                          "r"(b[ni][0]), "r"(b[ni][1]));
                }
        }
        __syncthreads();
    }

    // Writeback bf16 (c0,c1 adjacent columns -> one bf16x2 word)
    #pragma unroll
    for (int mi = 0; mi < 4; mi++) {
        int r0 = m0 + wm * 64 + mi * 16 + g;
        #pragma unroll
        for (int ni = 0; ni < 8; ni++) {
            int c = n0 + wn * 64 + ni * 8 + t * 2;
            *reinterpret_cast<uint32_t*>(g_y + (size_t)r0 * DDIM + c) =
                pack2(acc[mi][ni][0], acc[mi][ni][1]);
            *reinterpret_cast<uint32_t*>(g_y + (size_t)(r0 + 8) * DDIM + c) =
                pack2(acc[mi][ni][2], acc[mi][ni][3]);
        }
    }
}

// ---------------------------------------------------------------------------
// Fused epilogue: ONE WARP per row, zero __syncthreads.
// R14: bf16 y input, bf16-packed prototype registers, 128-reg budget (occ 4/SMSP).
// ---------------------------------------------------------------------------
__device__ __forceinline__ float wredsum(float x) {
    #pragma unroll
    for (int o = 16; o > 0; o >>= 1) x += __shfl_xor_sync(0xffffffffu, x, o);
    return x;
}
__device__ __forceinline__ float clampf(float x, float a) { return fminf(fmaxf(x, -a), a); }
__device__ __forceinline__ float4 c4(float4 v, float a) {
    return make_float4(clampf(v.x,a), clampf(v.y,a), clampf(v.z,a), clampf(v.w,a));
}

constexpr int EPI_WARPS = 4;   // rows per block

__global__ void __launch_bounds__(EPI_WARPS * 32, 4)
epilogue_kernel(const float* __restrict__ raw, const float* __restrict__ te,
                const float* __restrict__ protos, const float* __restrict__ bq,
                const float* __restrict__ Wg, const float* __restrict__ bg,
                const float* __restrict__ gam, const float* __restrict__ bet,
                const float* __restrict__ temperature, float* __restrict__ out) {
    const int lane = threadIdx.x & 31;
    const int row  = blockIdx.x * EPI_WARPS + (threadIdx.x >> 5);
    const size_t base4 = (size_t)row * (DDIM / 4);   // float4 units

    const uint2*  y2p = reinterpret_cast<const uint2*>(g_y) + base4;   // 4 bf16 per uint2
    const float4* r4p = reinterpret_cast<const float4*>(raw) + base4;
    const uint4*  p4p = reinterpret_cast<const uint4*>(protos) + (size_t)row * (NPROTO * DDIM / 4);
    const float4* bq4 = reinterpret_cast<const float4*>(bq);
    const float4* g4  = reinterpret_cast<const float4*>(gam);
    const float4* b4  = reinterpret_cast<const float4*>(bet);
    const float4* w4  = reinterpret_cast<const float4*>(Wg);

    // ---- LN1 input: y + bq ----
    float4 yv[4];
    float s0 = 0.f, s1 = 0.f;
    #pragma unroll
    for (int j = 0; j < 4; j++) {
        uint2 u = y2p[lane + 32 * j];
        float2 lo = unpack2(u.x), hi = unpack2(u.y);
        float4 b = bq4[lane + 32 * j];
        float4 v = make_float4(lo.x + b.x, lo.y + b.y, hi.x + b.z, hi.y + b.w);
        yv[j] = v;
        s0 += v.x + v.y + v.z + v.w;
        s1 += v.x*v.x + v.y*v.y + v.z*v.z + v.w*v.w;
    }
    s0 = wredsum(s0); s1 = wredsum(s1);
    float mean = s0 * (1.f / DDIM);
    float rstd = rsqrtf(s1 * (1.f / DDIM) - mean * mean + 1e-6f);

    // ---- q = tanh(LN(y)); |q|<=1 so the +-20 clip is a no-op ----
    float4 qv[4];
    float sqq = 0.f;
    #pragma unroll
    for (int j = 0; j < 4; j++) {
        float4 gm = g4[lane + 32 * j], bt = b4[lane + 32 * j];
        float4 q;
        q.x = tanhf((yv[j].x - mean) * rstd * gm.x + bt.x);
        q.y = tanhf((yv[j].y - mean) * rstd * gm.y + bt.y);
        q.z = tanhf((yv[j].z - mean) * rstd * gm.z + bt.z);
        q.w = tanhf((yv[j].w - mean) * rstd * gm.w + bt.w);
        qv[j] = q;
        sqq += q.x*q.x + q.y*q.y + q.z*q.z + q.w*q.w;
    }

    // ---- prototypes: loaded fp32, kept as bf16x2 in registers (40 regs) ----
    uint32_t pkb[NPROTO][8];
    float spp[NPROTO], sqp[NPROTO];
    #pragma unroll
    for (int k = 0; k < NPROTO; k++) {
        float app = 0.f, aqp = 0.f;
        #pragma unroll
        for (int j = 0; j < 4; j++) {
            uint4 u = p4p[k * (DDIM / 4) + lane + 32 * j];   // float4 as raw bits
            float4 v = make_float4(__uint_as_float(u.x), __uint_as_float(u.y),
                                   __uint_as_float(u.z), __uint_as_float(u.w));
            pkb[k][j * 2]     = pack2(v.x, v.y);
            pkb[k][j * 2 + 1] = pack2(v.z, v.w);
            float4 c = c4(v, 20.f);
            app += c.x*c.x + c.y*c.y + c.z*c.z + c.w*c.w;
            aqp += qv[j].x*c.x + qv[j].y*c.y + qv[j].z*c.z + qv[j].w*c.w;
        }
        spp[k] = app; sqp[k] = aqp;
    }
    sqq = wredsum(sqq);
    #pragma unroll
    for (int k = 0; k < NPROTO; k++) { spp[k] = wredsum(spp[k]); sqp[k] = wredsum(sqp[k]); }

    // ---- cosine -> softmax (K=5, redundant per lane) ----
    float qn  = fmaxf(sqrtf(sqq), 1e-6f);
    float tmp = fminf(fmaxf(temperature[0], 0.5f), 5.f) + 1e-4f;
    float sim[NPROTO], mx = -1e30f;
    #pragma unroll
    for (int k = 0; k < NPROTO; k++) {
        float pn = fmaxf(sqrtf(spp[k]), 1e-6f);
        sim[k] = clampf(sqp[k] / (qn * pn), 15.f) / tmp;
        mx = fmaxf(mx, sim[k]);
    }
    float den = 0.f;
    #pragma unroll
    for (int k = 0; k < NPROTO; k++) { sim[k] = __expf(sim[k] - mx); den += sim[k]; }
    float inv = 1.f / den;
    #pragma unroll
    for (int k = 0; k < NPROTO; k++) sim[k] *= inv;

    // ---- cand + gate partial ----
    float4 cand[4], rw[4];
    float gs = 0.f;
    #pragma unroll
    for (int j = 0; j < 4; j++) {
        float4 c = make_float4(0.f, 0.f, 0.f, 0.f);
        #pragma unroll
        for (int k = 0; k < NPROTO; k++) {
            float2 lo = unpack2(pkb[k][j * 2]), hi = unpack2(pkb[k][j * 2 + 1]);
            c.x += sim[k] * lo.x; c.y += sim[k] * lo.y;
            c.z += sim[k] * hi.x; c.w += sim[k] * hi.y;
        }
        c = c4(c, 5.f);
        cand[j] = c;
        float4 rv = c4(r4p[lane + 32 * j], 50.f);
        rw[j] = rv;
        float4 rc = c4(rv, 30.f);
        float4 wa = w4[lane + 32 * j];          // Wg[0:512]
        float4 wb = w4[128 + lane + 32 * j];    // Wg[512:1024]
        gs += wa.x*rc.x + wa.y*rc.y + wa.z*rc.z + wa.w*rc.w;
        gs += wb.x*c.x  + wb.y*c.y  + wb.z*c.z  + wb.w*c.w;
    }
    {   // time contribution: cols 0..127 live in j==0 slots
        float4 tv = c4(reinterpret_cast<const float4*>(te)[(size_t)row * (TDIM/4) + lane], 30.f);
        float4 wc = w4[256 + lane];             // Wg[1024:1152]
        gs += wc.x*tv.x + wc.y*tv.y + wc.z*tv.z + wc.w*tv.w;
    }
    gs = wredsum(gs);
    float logit = clampf(gs + bg[0], 10.f);
    float gg = 1.f / (1.f + __expf(-logit));

    // ---- blend + LN2 + clip ----
    float4 up[4];
    s0 = 0.f; s1 = 0.f;
    #pragma unroll
    for (int j = 0; j < 4; j++) {
        float4 u;
        u.x = 0.8f * rw[j].x + 0.2f * ((1.f - gg) * rw[j].x + gg * cand[j].x);
        u.y = 0.8f * rw[j].y + 0.2f * ((1.f - gg) * rw[j].y + gg * cand[j].y);
        u.z = 0.8f * rw[j].z + 0.2f * ((1.f - gg) * rw[j].z + gg * cand[j].z);
        u.w = 0.8f * rw[j].w + 0.2f * ((1.f - gg) * rw[j].w + gg * cand[j].w);
        up[j] = u;
        s0 += u.x + u.y + u.z + u.w;
        s1 += u.x*u.x + u.y*u.y + u.z*u.z + u.w*u.w;
    }
    s0 = wredsum(s0); s1 = wredsum(s1);
    mean = s0 * (1.f / DDIM);
    rstd = rsqrtf(s1 * (1.f / DDIM) - mean * mean + 1e-6f);
    float4* o4 = reinterpret_cast<float4*>(out) + base4;
    #pragma unroll
    for (int j = 0; j < 4; j++) {
        float4 gm = g4[lane + 32 * j], bt = b4[lane + 32 * j];
        float4 o;
        o.x = clampf((up[j].x - mean) * rstd * gm.x + bt.x, 10.f);
        o.y = clampf((up[j].y - mean) * rstd * gm.y + bt.y, 10.f);
        o.z = clampf((up[j].z - mean) * rstd * gm.z + bt.z, 10.f);
        o.w = clampf((up[j].w - mean) * rstd * gm.w + bt.w, 10.f);
        o4[lane + 32 * j] = o;
    }
}

// ---------------------------------------------------------------------------
extern "C" void kernel_launch(void* const* d_in, const int* in_sizes, int n_in,
                              void* d_out, int out_size) {
    (void)in_sizes; (void)n_in; (void)out_size;
    const float* raw  = (const float*)d_in[0];
    // d_in[1] = node_features: unused by the reference computation
    const float* edge = (const float*)d_in[2];
    const float* te   = (const float*)d_in[3];
    const float* prot = (const float*)d_in[4];
    const float* Wq   = (const float*)d_in[5];
    const float* bq   = (const float*)d_in[6];
    const float* Wg   = (const float*)d_in[7];
    const float* bg   = (const float*)d_in[8];
    const float* gam  = (const float*)d_in[9];
    const float* bet  = (const float*)d_in[10];
    const float* temp = (const float*)d_in[11];
    float* out = (float*)d_out;

    convB_kernel<<<(DDIM * KDIM / 4) / 256, 256>>>(Wq);
    gemm_kernel<<<dim3(2, 512), 256>>>(raw, edge, te);
    epilogue_kernel<<<NROWS / EPI_WARPS, EPI_WARPS * 32>>>(raw, te, prot, bq, Wg, bg, gam, bet, temp, out);
}